// round 1
// baseline (speedup 1.0000x reference)
#include <cuda_runtime.h>
#include <math.h>

#define Dm   2048
#define Hh   16
#define KVh  8
#define HD   128
#define Ff   8192
#define Vv   32000
#define MAXP 4096
#define Bb   4
#define Ll   2
#define EPS  1e-6f
#define ATT_SCALE 0.08838834764831845f   // 1/sqrt(128)
#define NCHUNK 16
#define CHUNK  256                        // MAXP / NCHUNK

// ---------------- scratch (allocation-free: __device__ globals) -------------
__device__ __align__(16) float g_x  [Dm*Bb];        // residual stream, [D][B]
__device__ __align__(16) float g_h  [Dm*Bb];        // rmsnormed, [D][B]
__device__ __align__(16) float g_qkv[4096*Bb];      // q(0..2047) k(2048..3071) v(3072..4095), [N][B]
__device__ __align__(16) float g_q  [Bb*Hh*HD];     // roped q, [B][H][HD]
__device__ __align__(16) float g_kn [Bb*KVh*HD];    // new k, [B][KV][HD]
__device__ __align__(16) float g_vn [Bb*KVh*HD];    // new v
__device__ __align__(16) float g_o  [Dm*Bb];        // attn out, [N][B]
__device__ __align__(16) float g_g  [Ff*Bb];        // mlp mid, [F][B]
__device__ __align__(16) float g_pacc[Bb*Hh*NCHUNK*HD];
__device__ float g_pm[Bb*Hh*NCHUNK];
__device__ float g_pl[Bb*Hh*NCHUNK];

// ---------------- embed -----------------------------------------------------
__global__ void embed_k(const int* __restrict__ tok, const float* __restrict__ emb,
                        float* __restrict__ x) {
    int d = blockIdx.x * blockDim.x + threadIdx.x;
    int b = blockIdx.y;
    x[d*Bb + b] = emb[(size_t)tok[b]*Dm + d];
}

// ---------------- rmsnorm on [D][B] layout ----------------------------------
__global__ void rmsnorm_k(const float* __restrict__ x, const float* __restrict__ w,
                          float* __restrict__ out, int D) {
    int b = blockIdx.x, tid = threadIdx.x;
    float ss = 0.f;
    for (int d = tid; d < D; d += 256) { float v = x[d*Bb + b]; ss += v*v; }
    __shared__ float sm[8];
    #pragma unroll
    for (int o = 16; o; o >>= 1) ss += __shfl_xor_sync(~0u, ss, o);
    if ((tid & 31) == 0) sm[tid >> 5] = ss;
    __syncthreads();
    float tot = 0.f;
    #pragma unroll
    for (int i = 0; i < 8; i++) tot += sm[i];
    float r = rsqrtf(tot / (float)D + EPS);
    for (int d = tid; d < D; d += 256) out[d*Bb + b] = x[d*Bb + b] * r * w[d];
}

// ---------------- batch-4 GEMV:  y[n][b] (+res) = sum_d x[d][b]*W[d][n] -----
// 256 thr: 4 along n (x float4 = 16 cols/block), 64 along d. W row-major [D][N].
template<bool RES, bool OUTBN>
__global__ void __launch_bounds__(256) gemv_k(
    const float* __restrict__ x, const float* __restrict__ W,
    float* __restrict__ y, int D, int N) {
    __shared__ float sred[256*17];
    int tid = threadIdx.x;
    int tn = tid & 3, td = tid >> 2;
    int nbase = blockIdx.x * 16;
    const float* Wp = W + nbase + tn*4;
    float4 a0 = {0,0,0,0}, a1 = a0, a2 = a0, a3 = a0;
    for (int d = td; d < D; d += 64) {
        float4 xv = *(const float4*)(x + d*Bb);
        float4 wv = *(const float4*)(Wp + (size_t)d*N);
        a0.x = fmaf(wv.x, xv.x, a0.x); a0.y = fmaf(wv.x, xv.y, a0.y);
        a0.z = fmaf(wv.x, xv.z, a0.z); a0.w = fmaf(wv.x, xv.w, a0.w);
        a1.x = fmaf(wv.y, xv.x, a1.x); a1.y = fmaf(wv.y, xv.y, a1.y);
        a1.z = fmaf(wv.y, xv.z, a1.z); a1.w = fmaf(wv.y, xv.w, a1.w);
        a2.x = fmaf(wv.z, xv.x, a2.x); a2.y = fmaf(wv.z, xv.y, a2.y);
        a2.z = fmaf(wv.z, xv.z, a2.z); a2.w = fmaf(wv.z, xv.w, a2.w);
        a3.x = fmaf(wv.w, xv.x, a3.x); a3.y = fmaf(wv.w, xv.y, a3.y);
        a3.z = fmaf(wv.w, xv.z, a3.z); a3.w = fmaf(wv.w, xv.w, a3.w);
    }
    float* s = &sred[tid*17];
    s[0]=a0.x; s[1]=a0.y; s[2]=a0.z; s[3]=a0.w;
    s[4]=a1.x; s[5]=a1.y; s[6]=a1.z; s[7]=a1.w;
    s[8]=a2.x; s[9]=a2.y; s[10]=a2.z; s[11]=a2.w;
    s[12]=a3.x; s[13]=a3.y; s[14]=a3.z; s[15]=a3.w;
    __syncthreads();
    if (tid < 64) {
        int tno = tid >> 4, j = tid & 15;
        float sum = 0.f;
        #pragma unroll 8
        for (int g = 0; g < 64; g++) sum += sred[(g*4 + tno)*17 + j];
        int c = j >> 2, b = j & 3;
        int n = nbase + tno*4 + c;
        if (OUTBN) {
            y[(size_t)b*N + n] = sum;
        } else {
            if (RES) sum += y[n*Bb + b];
            y[n*Bb + b] = sum;
        }
    }
}

// ---------------- fused gate/up GEMV + silu(g)*u -----------------------------
__global__ void __launch_bounds__(256) gemv_gateup_k(
    const float* __restrict__ x, const float* __restrict__ Wg,
    const float* __restrict__ Wu, float* __restrict__ y, int D, int N) {
    __shared__ float sred[256*17];
    int tid = threadIdx.x;
    int tn = tid & 3, td = tid >> 2;
    int nbase = blockIdx.x * 16;
    const float* Wgp = Wg + nbase + tn*4;
    const float* Wup = Wu + nbase + tn*4;
    float4 ga0 = {0,0,0,0}, ga1 = ga0, ga2 = ga0, ga3 = ga0;
    float4 ua0 = ga0, ua1 = ga0, ua2 = ga0, ua3 = ga0;
    for (int d = td; d < D; d += 64) {
        float4 xv = *(const float4*)(x + d*Bb);
        float4 wg = *(const float4*)(Wgp + (size_t)d*N);
        float4 wu = *(const float4*)(Wup + (size_t)d*N);
        ga0.x = fmaf(wg.x, xv.x, ga0.x); ga0.y = fmaf(wg.x, xv.y, ga0.y);
        ga0.z = fmaf(wg.x, xv.z, ga0.z); ga0.w = fmaf(wg.x, xv.w, ga0.w);
        ga1.x = fmaf(wg.y, xv.x, ga1.x); ga1.y = fmaf(wg.y, xv.y, ga1.y);
        ga1.z = fmaf(wg.y, xv.z, ga1.z); ga1.w = fmaf(wg.y, xv.w, ga1.w);
        ga2.x = fmaf(wg.z, xv.x, ga2.x); ga2.y = fmaf(wg.z, xv.y, ga2.y);
        ga2.z = fmaf(wg.z, xv.z, ga2.z); ga2.w = fmaf(wg.z, xv.w, ga2.w);
        ga3.x = fmaf(wg.w, xv.x, ga3.x); ga3.y = fmaf(wg.w, xv.y, ga3.y);
        ga3.z = fmaf(wg.w, xv.z, ga3.z); ga3.w = fmaf(wg.w, xv.w, ga3.w);
        ua0.x = fmaf(wu.x, xv.x, ua0.x); ua0.y = fmaf(wu.x, xv.y, ua0.y);
        ua0.z = fmaf(wu.x, xv.z, ua0.z); ua0.w = fmaf(wu.x, xv.w, ua0.w);
        ua1.x = fmaf(wu.y, xv.x, ua1.x); ua1.y = fmaf(wu.y, xv.y, ua1.y);
        ua1.z = fmaf(wu.y, xv.z, ua1.z); ua1.w = fmaf(wu.y, xv.w, ua1.w);
        ua2.x = fmaf(wu.z, xv.x, ua2.x); ua2.y = fmaf(wu.z, xv.y, ua2.y);
        ua2.z = fmaf(wu.z, xv.z, ua2.z); ua2.w = fmaf(wu.z, xv.w, ua2.w);
        ua3.x = fmaf(wu.w, xv.x, ua3.x); ua3.y = fmaf(wu.w, xv.y, ua3.y);
        ua3.z = fmaf(wu.w, xv.z, ua3.z); ua3.w = fmaf(wu.w, xv.w, ua3.w);
    }
    float* s = &sred[tid*17];
    s[0]=ga0.x; s[1]=ga0.y; s[2]=ga0.z; s[3]=ga0.w;
    s[4]=ga1.x; s[5]=ga1.y; s[6]=ga1.z; s[7]=ga1.w;
    s[8]=ga2.x; s[9]=ga2.y; s[10]=ga2.z; s[11]=ga2.w;
    s[12]=ga3.x; s[13]=ga3.y; s[14]=ga3.z; s[15]=ga3.w;
    __syncthreads();
    float sg = 0.f;
    if (tid < 64) {
        int tno = tid >> 4, j = tid & 15;
        #pragma unroll 8
        for (int g = 0; g < 64; g++) sg += sred[(g*4 + tno)*17 + j];
    }
    __syncthreads();
    s[0]=ua0.x; s[1]=ua0.y; s[2]=ua0.z; s[3]=ua0.w;
    s[4]=ua1.x; s[5]=ua1.y; s[6]=ua1.z; s[7]=ua1.w;
    s[8]=ua2.x; s[9]=ua2.y; s[10]=ua2.z; s[11]=ua2.w;
    s[12]=ua3.x; s[13]=ua3.y; s[14]=ua3.z; s[15]=ua3.w;
    __syncthreads();
    if (tid < 64) {
        int tno = tid >> 4, j = tid & 15;
        float su = 0.f;
        #pragma unroll 8
        for (int g = 0; g < 64; g++) su += sred[(g*4 + tno)*17 + j];
        int c = j >> 2, b = j & 3;
        int n = nbase + tno*4 + c;
        float silu = sg / (1.f + __expf(-sg));
        y[n*Bb + b] = silu * su;
    }
}

// ---------------- per-head q/k rmsnorm + rope + v transpose ------------------
__global__ void qkrope_k(const float* __restrict__ qkv, const float* __restrict__ qw,
                         const float* __restrict__ kw, const int* __restrict__ cpos,
                         float* __restrict__ qout, float* __restrict__ kout,
                         float* __restrict__ vout) {
    int b = blockIdx.x, r = blockIdx.y, t = threadIdx.x;   // t in [0,128)
    if (r >= Hh + KVh) {                                    // v rows: plain transpose
        int kv = r - Hh - KVh;
        vout[(b*KVh + kv)*HD + t] = qkv[(3072 + kv*HD + t)*Bb + b];
        return;
    }
    float val;
    if (r < Hh) val = qkv[(r*HD + t)*Bb + b];
    else        val = qkv[(2048 + (r - Hh)*HD + t)*Bb + b];
    // rmsnorm over the 128-dim head
    __shared__ float red[4];
    __shared__ float sv[HD];
    float ss = val * val;
    #pragma unroll
    for (int o = 16; o; o >>= 1) ss += __shfl_xor_sync(~0u, ss, o);
    if ((t & 31) == 0) red[t >> 5] = ss;
    __syncthreads();
    float tot = red[0] + red[1] + red[2] + red[3];
    float rr = rsqrtf(tot / (float)HD + EPS);
    const float* nw = (r < Hh) ? qw : kw;
    val = val * rr * nw[t];
    sv[t] = val;
    __syncthreads();
    int i = t & 63;
    float inv = 1.0f / powf(1.0e6f, (float)i / 64.0f);
    float ang = (float)cpos[0] * inv;
    float c = cosf(ang), s = sinf(ang);
    float other = (t < 64) ? sv[t + 64] : sv[t - 64];
    float o = (t < 64) ? (val * c - other * s) : (val * c + other * s);
    if (r < Hh) qout[(b*Hh + r)*HD + t] = o;
    else        kout[(b*KVh + (r - Hh))*HD + t] = o;
}

// ---------------- flash-decode attention, chunked over positions -------------
// block = (b, kv-head) serves both q-heads of the GQA group (halves KV traffic)
__global__ void attn_k(const float* __restrict__ kc, const float* __restrict__ vc,
                       const int* __restrict__ cpos, const float* __restrict__ qbuf,
                       const float* __restrict__ knew, const float* __restrict__ vnew,
                       float* __restrict__ pacc, float* __restrict__ pm,
                       float* __restrict__ pl) {
    int bkv = blockIdx.x, chunk = blockIdx.y;
    int b = bkv >> 3, kv = bkv & 7;
    int tid = threadIdx.x, w = tid >> 5, lane = tid & 31;
    int P = cpos[0];
    int start = chunk * CHUNK;
    int bh0 = b*Hh + kv*2;
    if (start > P) {   // chunk fully masked
        for (int i = tid; i < 2*HD; i += 128) {
            int hh = i >> 7, t = i & 127;
            pacc[((size_t)(bh0 + hh)*NCHUNK + chunk)*HD + t] = 0.f;
        }
        if (tid < 2) {
            pm[(bh0 + tid)*NCHUNK + chunk] = -1e30f;
            pl[(bh0 + tid)*NCHUNK + chunk] = 0.f;
        }
        return;
    }
    int end = min(start + CHUNK, P + 1);
    float4 q0 = *(const float4*)(qbuf + (bh0    )*HD + lane*4);
    float4 q1 = *(const float4*)(qbuf + (bh0 + 1)*HD + lane*4);
    const float* Kbase = kc + ((size_t)b*KVh + kv)*MAXP*HD;
    const float* Vbase = vc + ((size_t)b*KVh + kv)*MAXP*HD;
    const float* kn = knew + (b*KVh + kv)*HD;
    const float* vn = vnew + (b*KVh + kv)*HD;
    float m0 = -1e30f, m1 = -1e30f, l0 = 0.f, l1 = 0.f;
    float4 a0 = {0,0,0,0}, a1 = a0;
    for (int p = start + w; p < end; p += 4) {
        const float* Kp = (p == P) ? kn : Kbase + (size_t)p*HD;
        const float* Vp = (p == P) ? vn : Vbase + (size_t)p*HD;
        float4 kk = *(const float4*)(Kp + lane*4);
        float s0 = q0.x*kk.x + q0.y*kk.y + q0.z*kk.z + q0.w*kk.w;
        float s1 = q1.x*kk.x + q1.y*kk.y + q1.z*kk.z + q1.w*kk.w;
        #pragma unroll
        for (int o = 16; o; o >>= 1) {
            s0 += __shfl_xor_sync(~0u, s0, o);
            s1 += __shfl_xor_sync(~0u, s1, o);
        }
        s0 *= ATT_SCALE; s1 *= ATT_SCALE;
        float4 vv = *(const float4*)(Vp + lane*4);
        float mn0 = fmaxf(m0, s0), c0 = __expf(m0 - mn0), p0 = __expf(s0 - mn0);
        l0 = l0*c0 + p0;
        a0.x = a0.x*c0 + p0*vv.x; a0.y = a0.y*c0 + p0*vv.y;
        a0.z = a0.z*c0 + p0*vv.z; a0.w = a0.w*c0 + p0*vv.w;
        m0 = mn0;
        float mn1 = fmaxf(m1, s1), c1 = __expf(m1 - mn1), p1 = __expf(s1 - mn1);
        l1 = l1*c1 + p1;
        a1.x = a1.x*c1 + p1*vv.x; a1.y = a1.y*c1 + p1*vv.y;
        a1.z = a1.z*c1 + p1*vv.z; a1.w = a1.w*c1 + p1*vv.w;
        m1 = mn1;
    }
    __shared__ float sm_m[2][4], sm_l[2][4];
    __shared__ float sm_a[2][4][HD];
    if (lane == 0) { sm_m[0][w] = m0; sm_l[0][w] = l0; sm_m[1][w] = m1; sm_l[1][w] = l1; }
    *(float4*)&sm_a[0][w][lane*4] = a0;
    *(float4*)&sm_a[1][w][lane*4] = a1;
    __syncthreads();
    #pragma unroll
    for (int hh = 0; hh < 2; hh++) {
        float M = fmaxf(fmaxf(sm_m[hh][0], sm_m[hh][1]), fmaxf(sm_m[hh][2], sm_m[hh][3]));
        float L = 0.f, A = 0.f;
        #pragma unroll
        for (int ww = 0; ww < 4; ww++) {
            float e = __expf(sm_m[hh][ww] - M);
            L += sm_l[hh][ww] * e;
            A += sm_a[hh][ww][tid] * e;
        }
        pacc[((size_t)(bh0 + hh)*NCHUNK + chunk)*HD + tid] = A;
        if (tid == 0) {
            pm[(bh0 + hh)*NCHUNK + chunk] = M;
            pl[(bh0 + hh)*NCHUNK + chunk] = L;
        }
    }
}

__global__ void attn_comb_k(const float* __restrict__ pacc, const float* __restrict__ pm,
                            const float* __restrict__ pl, float* __restrict__ o) {
    int bh = blockIdx.x, t = threadIdx.x;
    int b = bh / Hh, h = bh % Hh;
    float M = -1e30f;
    #pragma unroll
    for (int c = 0; c < NCHUNK; c++) M = fmaxf(M, pm[bh*NCHUNK + c]);
    float L = 0.f, A = 0.f;
    #pragma unroll
    for (int c = 0; c < NCHUNK; c++) {
        float e = __expf(pm[bh*NCHUNK + c] - M);
        L += pl[bh*NCHUNK + c] * e;
        A += pacc[((size_t)bh*NCHUNK + c)*HD + t] * e;
    }
    o[(h*HD + t)*Bb + b] = A / L;
}

// ---------------- host orchestration ----------------------------------------
extern "C" void kernel_launch(void* const* d_in, const int* in_sizes, int n_in,
                              void* d_out, int out_size) {
    const int*   tok    = (const int*)  d_in[0];
    const int*   cpos   = (const int*)  d_in[1];
    const float* kcache = (const float*)d_in[2];
    const float* vcache = (const float*)d_in[3];
    const float* embw   = (const float*)d_in[4];
    const float* ln1    = (const float*)d_in[5];
    const float* wq     = (const float*)d_in[6];
    const float* wk     = (const float*)d_in[7];
    const float* wv     = (const float*)d_in[8];
    const float* qnw    = (const float*)d_in[9];
    const float* knw    = (const float*)d_in[10];
    const float* wo     = (const float*)d_in[11];
    const float* ln2    = (const float*)d_in[12];
    const float* wg     = (const float*)d_in[13];
    const float* wu     = (const float*)d_in[14];
    const float* wd     = (const float*)d_in[15];
    const float* fnw    = (const float*)d_in[16];
    const float* lmw    = (const float*)d_in[17];
    float* out = (float*)d_out;

    float *x, *h, *qkv, *q, *kn, *vn, *o, *g, *pacc, *pm, *pl;
    cudaGetSymbolAddress((void**)&x,    g_x);
    cudaGetSymbolAddress((void**)&h,    g_h);
    cudaGetSymbolAddress((void**)&qkv,  g_qkv);
    cudaGetSymbolAddress((void**)&q,    g_q);
    cudaGetSymbolAddress((void**)&kn,   g_kn);
    cudaGetSymbolAddress((void**)&vn,   g_vn);
    cudaGetSymbolAddress((void**)&o,    g_o);
    cudaGetSymbolAddress((void**)&g,    g_g);
    cudaGetSymbolAddress((void**)&pacc, g_pacc);
    cudaGetSymbolAddress((void**)&pm,   g_pm);
    cudaGetSymbolAddress((void**)&pl,   g_pl);

    embed_k<<<dim3(Dm/256, Bb), 256>>>(tok, embw, x);

    for (int l = 0; l < Ll; l++) {
        const float* wq_l = wq + (size_t)l*Dm*Hh*HD;
        const float* wk_l = wk + (size_t)l*Dm*KVh*HD;
        const float* wv_l = wv + (size_t)l*Dm*KVh*HD;
        const float* wo_l = wo + (size_t)l*Hh*HD*Dm;
        const float* wg_l = wg + (size_t)l*Dm*Ff;
        const float* wu_l = wu + (size_t)l*Dm*Ff;
        const float* wd_l = wd + (size_t)l*Ff*Dm;
        const float* kc_l = kcache + (size_t)l*Bb*KVh*MAXP*HD;
        const float* vc_l = vcache + (size_t)l*Bb*KVh*MAXP*HD;

        rmsnorm_k<<<Bb, 256>>>(x, ln1 + l*Dm, h, Dm);
        gemv_k<false,false><<<128, 256>>>(h, wq_l, qkv,            Dm, 2048);
        gemv_k<false,false><<<64,  256>>>(h, wk_l, qkv + 2048*Bb,  Dm, 1024);
        gemv_k<false,false><<<64,  256>>>(h, wv_l, qkv + 3072*Bb,  Dm, 1024);
        qkrope_k<<<dim3(Bb, Hh + 2*KVh), HD>>>(qkv, qnw + l*HD, knw + l*HD, cpos, q, kn, vn);
        attn_k<<<dim3(Bb*KVh, NCHUNK), 128>>>(kc_l, vc_l, cpos, q, kn, vn, pacc, pm, pl);
        attn_comb_k<<<Bb*Hh, HD>>>(pacc, pm, pl, o);
        gemv_k<true,false><<<128, 256>>>(o, wo_l, x, Dm, 2048);
        rmsnorm_k<<<Bb, 256>>>(x, ln2 + l*Dm, h, Dm);
        gemv_gateup_k<<<Ff/16, 256>>>(h, wg_l, wu_l, g, Dm, Ff);
        gemv_k<true,false><<<128, 256>>>(g, wd_l, x, Ff, 2048);
    }

    rmsnorm_k<<<Bb, 256>>>(x, fnw, h, Dm);
    gemv_k<false,true><<<Vv/16, 256>>>(h, lmw, out, Dm, Vv);
}

// round 2
// speedup vs baseline: 1.5958x; 1.5958x over previous
#include <cuda_runtime.h>
#include <math.h>

#define Dm   2048
#define Hh   16
#define KVh  8
#define HD   128
#define Ff   8192
#define Vv   32000
#define MAXP 4096
#define Bb   4
#define Ll   2
#define EPS  1e-6f
#define ATT_SCALE 0.08838834764831845f   // 1/sqrt(128)
#define NCHUNK 16
#define CHUNK  256                        // MAXP / NCHUNK

// ---------------- scratch (allocation-free: __device__ globals) -------------
__device__ __align__(16) float g_x  [Dm*Bb];        // residual stream, [D][B]
__device__ __align__(16) float g_h  [Dm*Bb];        // rmsnormed, [D][B]
__device__ __align__(16) float g_qkv[4096*Bb];      // q(0..2047) k(2048..3071) v(3072..4095), [N][B]
__device__ __align__(16) float g_q  [Bb*Hh*HD];     // roped q, [B][H][HD]
__device__ __align__(16) float g_kn [Bb*KVh*HD];    // new k, [B][KV][HD]
__device__ __align__(16) float g_vn [Bb*KVh*HD];    // new v
__device__ __align__(16) float g_o  [Dm*Bb];        // attn out, [N][B]
__device__ __align__(16) float g_g  [Ff*Bb];        // mlp mid, [F][B]
__device__ __align__(16) float g_pacc[Bb*Hh*NCHUNK*HD];
__device__ float g_pm[Bb*Hh*NCHUNK];
__device__ float g_pl[Bb*Hh*NCHUNK];

// ---------------- embed -----------------------------------------------------
__global__ void embed_k(const int* __restrict__ tok, const float* __restrict__ emb,
                        float* __restrict__ x) {
    int d = blockIdx.x * blockDim.x + threadIdx.x;
    int b = blockIdx.y;
    x[d*Bb + b] = emb[(size_t)tok[b]*Dm + d];
}

// ---------------- rmsnorm on [D][B] layout ----------------------------------
__global__ void rmsnorm_k(const float* __restrict__ x, const float* __restrict__ w,
                          float* __restrict__ out, int D) {
    int b = blockIdx.x, tid = threadIdx.x;
    float ss = 0.f;
    for (int d = tid; d < D; d += 256) { float v = x[d*Bb + b]; ss += v*v; }
    __shared__ float sm[8];
    #pragma unroll
    for (int o = 16; o; o >>= 1) ss += __shfl_xor_sync(~0u, ss, o);
    if ((tid & 31) == 0) sm[tid >> 5] = ss;
    __syncthreads();
    float tot = 0.f;
    #pragma unroll
    for (int i = 0; i < 8; i++) tot += sm[i];
    float r = rsqrtf(tot / (float)D + EPS);
    for (int d = tid; d < D; d += 256) out[d*Bb + b] = x[d*Bb + b] * r * w[d];
}

// =============================================================================
// batch-4 GEMV, 8 cols/block:  y[n][b] (+res) = sum_d x[d][b]*W[d][n]
// 256 thr: tn = tid&1 selects float4 col-group (2x4 = 8 cols), td = tid>>1
// strides rows. Warp rows cover 16 rows x 32B contiguous -> full sectors.
// Reduce: xor-shuffle over same-parity lanes, then 8-warp smem combine.
// =============================================================================
#define GEMV_ACC \
        a0.x = fmaf(wv.x, xv.x, a0.x); a0.y = fmaf(wv.x, xv.y, a0.y); \
        a0.z = fmaf(wv.x, xv.z, a0.z); a0.w = fmaf(wv.x, xv.w, a0.w); \
        a1.x = fmaf(wv.y, xv.x, a1.x); a1.y = fmaf(wv.y, xv.y, a1.y); \
        a1.z = fmaf(wv.y, xv.z, a1.z); a1.w = fmaf(wv.y, xv.w, a1.w); \
        a2.x = fmaf(wv.z, xv.x, a2.x); a2.y = fmaf(wv.z, xv.y, a2.y); \
        a2.z = fmaf(wv.z, xv.z, a2.z); a2.w = fmaf(wv.z, xv.w, a2.w); \
        a3.x = fmaf(wv.w, xv.x, a3.x); a3.y = fmaf(wv.w, xv.y, a3.y); \
        a3.z = fmaf(wv.w, xv.z, a3.z); a3.w = fmaf(wv.w, xv.w, a3.w);

#define SHFL16(o) \
        a0.x += __shfl_xor_sync(~0u, a0.x, o); a0.y += __shfl_xor_sync(~0u, a0.y, o); \
        a0.z += __shfl_xor_sync(~0u, a0.z, o); a0.w += __shfl_xor_sync(~0u, a0.w, o); \
        a1.x += __shfl_xor_sync(~0u, a1.x, o); a1.y += __shfl_xor_sync(~0u, a1.y, o); \
        a1.z += __shfl_xor_sync(~0u, a1.z, o); a1.w += __shfl_xor_sync(~0u, a1.w, o); \
        a2.x += __shfl_xor_sync(~0u, a2.x, o); a2.y += __shfl_xor_sync(~0u, a2.y, o); \
        a2.z += __shfl_xor_sync(~0u, a2.z, o); a2.w += __shfl_xor_sync(~0u, a2.w, o); \
        a3.x += __shfl_xor_sync(~0u, a3.x, o); a3.y += __shfl_xor_sync(~0u, a3.y, o); \
        a3.z += __shfl_xor_sync(~0u, a3.z, o); a3.w += __shfl_xor_sync(~0u, a3.w, o);

__device__ __forceinline__ void gemv8_core(
    const float* __restrict__ x, const float* __restrict__ W,
    int D, int N, int n0, float* __restrict__ smrow /* [16][17] */) {
    int tid = threadIdx.x;
    int tn = tid & 1, td = tid >> 1, w = tid >> 5, lane = tid & 31;
    const float* Wp = W + n0 + tn*4;
    float4 a0 = {0,0,0,0}, a1 = a0, a2 = a0, a3 = a0;
    #pragma unroll 8
    for (int d = td; d < D; d += 128) {
        float4 xv = *(const float4*)(x + d*Bb);
        float4 wv = *(const float4*)(Wp + (size_t)d*N);
        GEMV_ACC
    }
    SHFL16(16) SHFL16(8) SHFL16(4) SHFL16(2)
    if (lane < 2) {
        float* s = smrow + (w*2 + tn)*17;
        s[0]=a0.x; s[1]=a0.y; s[2]=a0.z; s[3]=a0.w;
        s[4]=a1.x; s[5]=a1.y; s[6]=a1.z; s[7]=a1.w;
        s[8]=a2.x; s[9]=a2.y; s[10]=a2.z; s[11]=a2.w;
        s[12]=a3.x; s[13]=a3.y; s[14]=a3.z; s[15]=a3.w;
    }
}

template<bool RES, bool OUTBN>
__global__ void __launch_bounds__(256) gemv8_k(
    const float* __restrict__ x, const float* __restrict__ W,
    float* __restrict__ y, int D, int N) {
    __shared__ float sred[16*17];
    int n0 = blockIdx.x * 8;
    gemv8_core(x, W, D, N, n0, sred);
    __syncthreads();
    int tid = threadIdx.x;
    if (tid < 32) {
        int tno = tid >> 4, j = tid & 15;
        float s = 0.f;
        #pragma unroll
        for (int ww = 0; ww < 8; ww++) s += sred[(ww*2 + tno)*17 + j];
        int c = j >> 2, b = j & 3;
        int n = n0 + tno*4 + c;
        if (OUTBN) {
            y[(size_t)b*N + n] = s;
        } else {
            if (RES) s += y[n*Bb + b];
            y[n*Bb + b] = s;
        }
    }
}

// fused q/k/v projection: one launch, 512 blocks (q:256 k:128 v:128)
__global__ void __launch_bounds__(256) gemv8_qkv_k(
    const float* __restrict__ x, const float* __restrict__ wq,
    const float* __restrict__ wk, const float* __restrict__ wv,
    float* __restrict__ qkv) {
    __shared__ float sred[16*17];
    int nb = blockIdx.x;
    const float* W; float* y; int N, n0;
    if (nb < 256)      { W = wq; y = qkv;           N = 2048; n0 = nb*8; }
    else if (nb < 384) { W = wk; y = qkv + 2048*Bb; N = 1024; n0 = (nb-256)*8; }
    else               { W = wv; y = qkv + 3072*Bb; N = 1024; n0 = (nb-384)*8; }
    gemv8_core(x, W, Dm, N, n0, sred);
    __syncthreads();
    int tid = threadIdx.x;
    if (tid < 32) {
        int tno = tid >> 4, j = tid & 15;
        float s = 0.f;
        #pragma unroll
        for (int ww = 0; ww < 8; ww++) s += sred[(ww*2 + tno)*17 + j];
        int c = j >> 2, b = j & 3;
        int n = n0 + tno*4 + c;
        y[n*Bb + b] = s;
    }
}

// fused gate/up GEMV + silu(g)*u, 8 cols/block -> Ff/8 = 1024 blocks
__global__ void __launch_bounds__(256) gemv8_gateup_k(
    const float* __restrict__ x, const float* __restrict__ Wg,
    const float* __restrict__ Wu, float* __restrict__ y, int D, int N) {
    __shared__ float sred[16*33];
    int tid = threadIdx.x;
    int tn = tid & 1, td = tid >> 1, w = tid >> 5, lane = tid & 31;
    int n0 = blockIdx.x * 8;
    const float* Wgp = Wg + n0 + tn*4;
    const float* Wup = Wu + n0 + tn*4;
    float4 ga0 = {0,0,0,0}, ga1 = ga0, ga2 = ga0, ga3 = ga0;
    float4 ua0 = ga0, ua1 = ga0, ua2 = ga0, ua3 = ga0;
    #pragma unroll 4
    for (int d = td; d < D; d += 128) {
        float4 xv = *(const float4*)(x + d*Bb);
        float4 wv = *(const float4*)(Wgp + (size_t)d*N);
        {
            float4 &a0 = ga0, &a1 = ga1, &a2 = ga2, &a3 = ga3;
            GEMV_ACC
        }
        wv = *(const float4*)(Wup + (size_t)d*N);
        {
            float4 &a0 = ua0, &a1 = ua1, &a2 = ua2, &a3 = ua3;
            GEMV_ACC
        }
    }
    {
        float4 &a0 = ga0, &a1 = ga1, &a2 = ga2, &a3 = ga3;
        SHFL16(16) SHFL16(8) SHFL16(4) SHFL16(2)
    }
    {
        float4 &a0 = ua0, &a1 = ua1, &a2 = ua2, &a3 = ua3;
        SHFL16(16) SHFL16(8) SHFL16(4) SHFL16(2)
    }
    if (lane < 2) {
        float* s = &sred[(w*2 + tn)*33];
        s[0]=ga0.x; s[1]=ga0.y; s[2]=ga0.z; s[3]=ga0.w;
        s[4]=ga1.x; s[5]=ga1.y; s[6]=ga1.z; s[7]=ga1.w;
        s[8]=ga2.x; s[9]=ga2.y; s[10]=ga2.z; s[11]=ga2.w;
        s[12]=ga3.x; s[13]=ga3.y; s[14]=ga3.z; s[15]=ga3.w;
        s[16]=ua0.x; s[17]=ua0.y; s[18]=ua0.z; s[19]=ua0.w;
        s[20]=ua1.x; s[21]=ua1.y; s[22]=ua1.z; s[23]=ua1.w;
        s[24]=ua2.x; s[25]=ua2.y; s[26]=ua2.z; s[27]=ua2.w;
        s[28]=ua3.x; s[29]=ua3.y; s[30]=ua3.z; s[31]=ua3.w;
    }
    __syncthreads();
    if (tid < 32) {
        int tno = tid >> 4, j = tid & 15;
        float sg = 0.f, su = 0.f;
        #pragma unroll
        for (int ww = 0; ww < 8; ww++) {
            sg += sred[(ww*2 + tno)*33 + j];
            su += sred[(ww*2 + tno)*33 + 16 + j];
        }
        int c = j >> 2, b = j & 3;
        int n = n0 + tno*4 + c;
        float silu = sg / (1.f + __expf(-sg));
        y[n*Bb + b] = silu * su;
    }
}

// ---------------- per-head q/k rmsnorm + rope + v transpose ------------------
__global__ void qkrope_k(const float* __restrict__ qkv, const float* __restrict__ qw,
                         const float* __restrict__ kw, const int* __restrict__ cpos,
                         float* __restrict__ qout, float* __restrict__ kout,
                         float* __restrict__ vout) {
    int b = blockIdx.x, r = blockIdx.y, t = threadIdx.x;   // t in [0,128)
    if (r >= Hh + KVh) {                                    // v rows: plain transpose
        int kv = r - Hh - KVh;
        vout[(b*KVh + kv)*HD + t] = qkv[(3072 + kv*HD + t)*Bb + b];
        return;
    }
    float val;
    if (r < Hh) val = qkv[(r*HD + t)*Bb + b];
    else        val = qkv[(2048 + (r - Hh)*HD + t)*Bb + b];
    // rmsnorm over the 128-dim head
    __shared__ float red[4];
    __shared__ float sv[HD];
    float ss = val * val;
    #pragma unroll
    for (int o = 16; o; o >>= 1) ss += __shfl_xor_sync(~0u, ss, o);
    if ((t & 31) == 0) red[t >> 5] = ss;
    __syncthreads();
    float tot = red[0] + red[1] + red[2] + red[3];
    float rr = rsqrtf(tot / (float)HD + EPS);
    const float* nw = (r < Hh) ? qw : kw;
    val = val * rr * nw[t];
    sv[t] = val;
    __syncthreads();
    int i = t & 63;
    float inv = 1.0f / powf(1.0e6f, (float)i / 64.0f);
    float ang = (float)cpos[0] * inv;
    float c = cosf(ang), s = sinf(ang);
    float other = (t < 64) ? sv[t + 64] : sv[t - 64];
    float o = (t < 64) ? (val * c - other * s) : (val * c + other * s);
    if (r < Hh) qout[(b*Hh + r)*HD + t] = o;
    else        kout[(b*KVh + (r - Hh))*HD + t] = o;
}

// ---------------- flash-decode attention, chunked over positions -------------
__global__ void attn_k(const float* __restrict__ kc, const float* __restrict__ vc,
                       const int* __restrict__ cpos, const float* __restrict__ qbuf,
                       const float* __restrict__ knew, const float* __restrict__ vnew,
                       float* __restrict__ pacc, float* __restrict__ pm,
                       float* __restrict__ pl) {
    int bkv = blockIdx.x, chunk = blockIdx.y;
    int b = bkv >> 3, kv = bkv & 7;
    int tid = threadIdx.x, w = tid >> 5, lane = tid & 31;
    int P = cpos[0];
    int start = chunk * CHUNK;
    int bh0 = b*Hh + kv*2;
    if (start > P) {   // chunk fully masked
        for (int i = tid; i < 2*HD; i += 128) {
            int hh = i >> 7, t = i & 127;
            pacc[((size_t)(bh0 + hh)*NCHUNK + chunk)*HD + t] = 0.f;
        }
        if (tid < 2) {
            pm[(bh0 + tid)*NCHUNK + chunk] = -1e30f;
            pl[(bh0 + tid)*NCHUNK + chunk] = 0.f;
        }
        return;
    }
    int end = min(start + CHUNK, P + 1);
    float4 q0 = *(const float4*)(qbuf + (bh0    )*HD + lane*4);
    float4 q1 = *(const float4*)(qbuf + (bh0 + 1)*HD + lane*4);
    const float* Kbase = kc + ((size_t)b*KVh + kv)*MAXP*HD;
    const float* Vbase = vc + ((size_t)b*KVh + kv)*MAXP*HD;
    const float* kn = knew + (b*KVh + kv)*HD;
    const float* vn = vnew + (b*KVh + kv)*HD;
    float m0 = -1e30f, m1 = -1e30f, l0 = 0.f, l1 = 0.f;
    float4 a0 = {0,0,0,0}, a1 = a0;
    for (int p = start + w; p < end; p += 4) {
        const float* Kp = (p == P) ? kn : Kbase + (size_t)p*HD;
        const float* Vp = (p == P) ? vn : Vbase + (size_t)p*HD;
        float4 kk = *(const float4*)(Kp + lane*4);
        float s0 = q0.x*kk.x + q0.y*kk.y + q0.z*kk.z + q0.w*kk.w;
        float s1 = q1.x*kk.x + q1.y*kk.y + q1.z*kk.z + q1.w*kk.w;
        #pragma unroll
        for (int o = 16; o; o >>= 1) {
            s0 += __shfl_xor_sync(~0u, s0, o);
            s1 += __shfl_xor_sync(~0u, s1, o);
        }
        s0 *= ATT_SCALE; s1 *= ATT_SCALE;
        float4 vv = *(const float4*)(Vp + lane*4);
        float mn0 = fmaxf(m0, s0), c0 = __expf(m0 - mn0), p0 = __expf(s0 - mn0);
        l0 = l0*c0 + p0;
        a0.x = a0.x*c0 + p0*vv.x; a0.y = a0.y*c0 + p0*vv.y;
        a0.z = a0.z*c0 + p0*vv.z; a0.w = a0.w*c0 + p0*vv.w;
        m0 = mn0;
        float mn1 = fmaxf(m1, s1), c1 = __expf(m1 - mn1), p1 = __expf(s1 - mn1);
        l1 = l1*c1 + p1;
        a1.x = a1.x*c1 + p1*vv.x; a1.y = a1.y*c1 + p1*vv.y;
        a1.z = a1.z*c1 + p1*vv.z; a1.w = a1.w*c1 + p1*vv.w;
        m1 = mn1;
    }
    __shared__ float sm_m[2][4], sm_l[2][4];
    __shared__ float sm_a[2][4][HD];
    if (lane == 0) { sm_m[0][w] = m0; sm_l[0][w] = l0; sm_m[1][w] = m1; sm_l[1][w] = l1; }
    *(float4*)&sm_a[0][w][lane*4] = a0;
    *(float4*)&sm_a[1][w][lane*4] = a1;
    __syncthreads();
    #pragma unroll
    for (int hh = 0; hh < 2; hh++) {
        float M = fmaxf(fmaxf(sm_m[hh][0], sm_m[hh][1]), fmaxf(sm_m[hh][2], sm_m[hh][3]));
        float L = 0.f, A = 0.f;
        #pragma unroll
        for (int ww = 0; ww < 4; ww++) {
            float e = __expf(sm_m[hh][ww] - M);
            L += sm_l[hh][ww] * e;
            A += sm_a[hh][ww][tid] * e;
        }
        pacc[((size_t)(bh0 + hh)*NCHUNK + chunk)*HD + tid] = A;
        if (tid == 0) {
            pm[(bh0 + hh)*NCHUNK + chunk] = M;
            pl[(bh0 + hh)*NCHUNK + chunk] = L;
        }
    }
}

__global__ void attn_comb_k(const float* __restrict__ pacc, const float* __restrict__ pm,
                            const float* __restrict__ pl, float* __restrict__ o) {
    int bh = blockIdx.x, t = threadIdx.x;
    int b = bh / Hh, h = bh % Hh;
    float M = -1e30f;
    #pragma unroll
    for (int c = 0; c < NCHUNK; c++) M = fmaxf(M, pm[bh*NCHUNK + c]);
    float L = 0.f, A = 0.f;
    #pragma unroll
    for (int c = 0; c < NCHUNK; c++) {
        float e = __expf(pm[bh*NCHUNK + c] - M);
        L += pl[bh*NCHUNK + c] * e;
        A += pacc[((size_t)bh*NCHUNK + c)*HD + t] * e;
    }
    o[(h*HD + t)*Bb + b] = A / L;
}

// ---------------- host orchestration ----------------------------------------
extern "C" void kernel_launch(void* const* d_in, const int* in_sizes, int n_in,
                              void* d_out, int out_size) {
    const int*   tok    = (const int*)  d_in[0];
    const int*   cpos   = (const int*)  d_in[1];
    const float* kcache = (const float*)d_in[2];
    const float* vcache = (const float*)d_in[3];
    const float* embw   = (const float*)d_in[4];
    const float* ln1    = (const float*)d_in[5];
    const float* wq     = (const float*)d_in[6];
    const float* wk     = (const float*)d_in[7];
    const float* wv     = (const float*)d_in[8];
    const float* qnw    = (const float*)d_in[9];
    const float* knw    = (const float*)d_in[10];
    const float* wo     = (const float*)d_in[11];
    const float* ln2    = (const float*)d_in[12];
    const float* wg     = (const float*)d_in[13];
    const float* wu     = (const float*)d_in[14];
    const float* wd     = (const float*)d_in[15];
    const float* fnw    = (const float*)d_in[16];
    const float* lmw    = (const float*)d_in[17];
    float* out = (float*)d_out;

    float *x, *h, *qkv, *q, *kn, *vn, *o, *g, *pacc, *pm, *pl;
    cudaGetSymbolAddress((void**)&x,    g_x);
    cudaGetSymbolAddress((void**)&h,    g_h);
    cudaGetSymbolAddress((void**)&qkv,  g_qkv);
    cudaGetSymbolAddress((void**)&q,    g_q);
    cudaGetSymbolAddress((void**)&kn,   g_kn);
    cudaGetSymbolAddress((void**)&vn,   g_vn);
    cudaGetSymbolAddress((void**)&o,    g_o);
    cudaGetSymbolAddress((void**)&g,    g_g);
    cudaGetSymbolAddress((void**)&pacc, g_pacc);
    cudaGetSymbolAddress((void**)&pm,   g_pm);
    cudaGetSymbolAddress((void**)&pl,   g_pl);

    embed_k<<<dim3(Dm/256, Bb), 256>>>(tok, embw, x);

    for (int l = 0; l < Ll; l++) {
        const float* wq_l = wq + (size_t)l*Dm*Hh*HD;
        const float* wk_l = wk + (size_t)l*Dm*KVh*HD;
        const float* wv_l = wv + (size_t)l*Dm*KVh*HD;
        const float* wo_l = wo + (size_t)l*Hh*HD*Dm;
        const float* wg_l = wg + (size_t)l*Dm*Ff;
        const float* wu_l = wu + (size_t)l*Dm*Ff;
        const float* wd_l = wd + (size_t)l*Ff*Dm;
        const float* kc_l = kcache + (size_t)l*Bb*KVh*MAXP*HD;
        const float* vc_l = vcache + (size_t)l*Bb*KVh*MAXP*HD;

        rmsnorm_k<<<Bb, 256>>>(x, ln1 + l*Dm, h, Dm);
        gemv8_qkv_k<<<512, 256>>>(h, wq_l, wk_l, wv_l, qkv);
        qkrope_k<<<dim3(Bb, Hh + 2*KVh), HD>>>(qkv, qnw + l*HD, knw + l*HD, cpos, q, kn, vn);
        attn_k<<<dim3(Bb*KVh, NCHUNK), 128>>>(kc_l, vc_l, cpos, q, kn, vn, pacc, pm, pl);
        attn_comb_k<<<Bb*Hh, HD>>>(pacc, pm, pl, o);
        gemv8_k<true,false><<<256, 256>>>(o, wo_l, x, Dm, 2048);
        rmsnorm_k<<<Bb, 256>>>(x, ln2 + l*Dm, h, Dm);
        gemv8_gateup_k<<<Ff/8, 256>>>(h, wg_l, wu_l, g, Dm, Ff);
        gemv8_k<true,false><<<256, 256>>>(g, wd_l, x, Ff, 2048);
    }

    rmsnorm_k<<<Bb, 256>>>(x, fnw, h, Dm);
    gemv8_k<false,true><<<Vv/8, 256>>>(h, lmw, out, Dm, Vv);
}